// round 2
// baseline (speedup 1.0000x reference)
#include <cuda_runtime.h>

#define T_ 64
#define S_ 400
#define B_ 32
#define H_ 512
#define E_ 1024
#define I_ 128
#define G3_ 1536
#define KSPLIT 8

// ---------------- persistent device scratch ----------------
__device__ float g_Wh[(size_t)S_ * B_ * E_];      // 52.4 MB : enc @ W_h^T
__device__ float g_gi1[(size_t)T_ * B_ * G3_];    // 12.6 MB : emb @ w_ih1^T + b_ih1
__device__ float g_h[B_ * H_];
__device__ float g_s1[B_ * H_];
__device__ float g_base[B_ * E_];                 // s1 @ W_s^T + b_attn
__device__ float g_score[B_ * S_];
__device__ float g_aw[B_ * S_];
__device__ float g_cov[B_ * S_];
__device__ float g_ctx[B_ * E_];
__device__ float g_p_gh1[KSPLIT * B_ * G3_];
__device__ float g_p_base[KSPLIT * B_ * E_];
__device__ float g_p_gh2[KSPLIT * B_ * G3_];
__device__ float g_p_gi2[KSPLIT * B_ * G3_];

// ---------------- math helpers ----------------
__device__ __forceinline__ float fast_tanh(float x) {
    // 1 - 2/(e^{2x}+1): accurate to ~1e-6 with __expf, correct saturation at +-inf
    float e = __expf(2.0f * x);
    return 1.0f - __fdividef(2.0f, e + 1.0f);
}
__device__ __forceinline__ float fast_sigmoid(float x) {
    return __fdividef(1.0f, 1.0f + __expf(-x));
}

// ---------------- init: state, coverage, x_indexes output ----------------
__global__ void k_init(const float* __restrict__ init_state,
                       const float* __restrict__ init_cov,
                       const int* __restrict__ x_index,
                       float* __restrict__ out_xi) {
    int i = blockIdx.x * blockDim.x + threadIdx.x;
    if (i < B_ * H_) g_h[i] = init_state[i];
    if (i < B_ * S_) g_cov[i] = init_cov[i];
    // out_xi[t][b][s] = x_index[s][b]
    for (int j = i; j < T_ * B_ * S_; j += gridDim.x * blockDim.x) {
        int s = j % S_;
        int b = (j / S_) % B_;
        out_xi[j] = (float)x_index[s * B_ + b];
    }
}

// ---------------- big SGEMM: C[M][N] = A[M][K] @ W[N][K]^T (+bias[n]) ----------------
// BM=BN=128, BK=8, TM=TN=8, 256 threads. M%128==0, N%128==0, K%8==0.
__global__ __launch_bounds__(256) void k_sgemm_nt(
    const float* __restrict__ A, const float* __restrict__ W,
    const float* __restrict__ bias, float* __restrict__ C,
    int M, int N, int K) {
    __shared__ float As[8][128];
    __shared__ float Bs[8][128];
    const int m0 = blockIdx.y * 128;
    const int n0 = blockIdx.x * 128;
    const int tid = threadIdx.x;
    const int tm = (tid / 16) * 8;
    const int tn = (tid % 16) * 8;
    const int lr = tid >> 1;            // 0..127 (tile row for loads)
    const int lc = (tid & 1) * 4;       // 0 or 4 (k offset for loads)

    float acc[8][8];
#pragma unroll
    for (int i = 0; i < 8; i++)
#pragma unroll
        for (int j = 0; j < 8; j++) acc[i][j] = 0.0f;

    for (int k0 = 0; k0 < K; k0 += 8) {
        float4 va = *(const float4*)&A[(size_t)(m0 + lr) * K + k0 + lc];
        float4 vb = *(const float4*)&W[(size_t)(n0 + lr) * K + k0 + lc];
        As[lc + 0][lr] = va.x; As[lc + 1][lr] = va.y; As[lc + 2][lr] = va.z; As[lc + 3][lr] = va.w;
        Bs[lc + 0][lr] = vb.x; Bs[lc + 1][lr] = vb.y; Bs[lc + 2][lr] = vb.z; Bs[lc + 3][lr] = vb.w;
        __syncthreads();
#pragma unroll
        for (int kk = 0; kk < 8; kk++) {
            float a[8], b[8];
#pragma unroll
            for (int i = 0; i < 8; i++) a[i] = As[kk][tm + i];
#pragma unroll
            for (int j = 0; j < 8; j++) b[j] = Bs[kk][tn + j];
#pragma unroll
            for (int i = 0; i < 8; i++)
#pragma unroll
                for (int j = 0; j < 8; j++) acc[i][j] += a[i] * b[j];
        }
        __syncthreads();
    }
    float bfrag[8];
#pragma unroll
    for (int j = 0; j < 8; j++) bfrag[j] = bias ? bias[n0 + tn + j] : 0.0f;
#pragma unroll
    for (int i = 0; i < 8; i++) {
        size_t row = (size_t)(m0 + tm + i) * N + n0 + tn;
#pragma unroll
        for (int j = 0; j < 8; j++) C[row + j] = acc[i][j] + bfrag[j];
    }
}

// ---------------- small batch-32 GEMM with split-K ----------------
// part[c][b][n] = sum_{k in chunk c} X[b][k] * W[n][k]
// grid (N/128, KSPLIT), 256 threads. K/KSPLIT must be a multiple of 32.
__global__ __launch_bounds__(256) void k_gemm_smallB(
    const float* __restrict__ X, const float* __restrict__ W,
    float* __restrict__ part, int N, int K) {
    const int KC = K / KSPLIT;
    const int n0 = blockIdx.x * 128;
    const int kc = blockIdx.y;
    const int k0 = kc * KC;
    const int tid = threadIdx.x;
    const int j = tid & 127;     // gate/output row within tile
    const int bg = tid >> 7;     // 0/1 -> b range of 16

    __shared__ float ws[128][33];
    __shared__ float xs[32][36];

    float acc[16];
#pragma unroll
    for (int u = 0; u < 16; u++) acc[u] = 0.0f;

    for (int kt = 0; kt < KC; kt += 32) {
        // W tile: 128 rows x 32 k, coalesced float4
        {
            int r = tid >> 1;
            int cb = (tid & 1) * 16;
#pragma unroll
            for (int u = 0; u < 4; u++) {
                float4 v = *(const float4*)&W[(size_t)(n0 + r) * K + k0 + kt + cb + u * 4];
                ws[r][cb + u * 4 + 0] = v.x; ws[r][cb + u * 4 + 1] = v.y;
                ws[r][cb + u * 4 + 2] = v.z; ws[r][cb + u * 4 + 3] = v.w;
            }
        }
        // X tile transposed: xs[kk][b]
        {
            int b = tid >> 3;
            int c = (tid & 7) * 4;
            float4 v = *(const float4*)&X[(size_t)b * K + k0 + kt + c];
            xs[c + 0][b] = v.x; xs[c + 1][b] = v.y; xs[c + 2][b] = v.z; xs[c + 3][b] = v.w;
        }
        __syncthreads();
#pragma unroll
        for (int kk = 0; kk < 32; kk++) {
            float wv = ws[j][kk];
            const float4* xr = (const float4*)&xs[kk][bg * 16];
            float4 x0 = xr[0], x1 = xr[1], x2 = xr[2], x3 = xr[3];
            acc[0]  += wv * x0.x; acc[1]  += wv * x0.y; acc[2]  += wv * x0.z; acc[3]  += wv * x0.w;
            acc[4]  += wv * x1.x; acc[5]  += wv * x1.y; acc[6]  += wv * x1.z; acc[7]  += wv * x1.w;
            acc[8]  += wv * x2.x; acc[9]  += wv * x2.y; acc[10] += wv * x2.z; acc[11] += wv * x2.w;
            acc[12] += wv * x3.x; acc[13] += wv * x3.y; acc[14] += wv * x3.z; acc[15] += wv * x3.w;
        }
        __syncthreads();
    }
    float* p = part + ((size_t)kc * B_ + bg * 16) * N + n0 + j;
#pragma unroll
    for (int u = 0; u < 16; u++) p[(size_t)u * N] = acc[u];
}

// ---------------- GRU1 finish: reduce split-K, gates, mask ----------------
__global__ void k_gru1_finish(const float* __restrict__ b_hh1,
                              const float* __restrict__ y_mask, int t) {
    int i = blockIdx.x * blockDim.x + threadIdx.x;  // B*H
    if (i >= B_ * H_) return;
    int b = i / H_, idx = i % H_;
    float h = g_h[i];
    const float* gi = g_gi1 + ((size_t)t * B_ + b) * G3_;
    float gir = gi[idx], giz = gi[H_ + idx], gin = gi[2 * H_ + idx];
    float ghr = b_hh1[idx], ghz = b_hh1[H_ + idx], ghn = b_hh1[2 * H_ + idx];
#pragma unroll
    for (int c = 0; c < KSPLIT; c++) {
        const float* p = g_p_gh1 + ((size_t)c * B_ + b) * G3_;
        ghr += p[idx]; ghz += p[H_ + idx]; ghn += p[2 * H_ + idx];
    }
    float r = fast_sigmoid(gir + ghr);
    float z = fast_sigmoid(giz + ghz);
    float n = fast_tanh(gin + r * ghn);
    float s = (1.0f - z) * n + z * h;
    float ym = y_mask[t * B_ + b];
    g_s1[i] = ym * s + (1.0f - ym) * h;
}

// ---------------- base finish: reduce split-K + b_attn ----------------
__global__ void k_base_finish(const float* __restrict__ b_attn) {
    int i = blockIdx.x * blockDim.x + threadIdx.x;  // B*E
    if (i >= B_ * E_) return;
    int b = i / E_, f = i % E_;
    float v = b_attn[f];
#pragma unroll
    for (int c = 0; c < KSPLIT; c++)
        v += g_p_base[((size_t)c * B_ + b) * E_ + f];
    g_base[i] = v;
}

// ---------------- attention score: warp per (s,b) ----------------
__global__ __launch_bounds__(256) void k_score(
    const float* __restrict__ x_mask, const float* __restrict__ W_c,
    const float* __restrict__ V) {
    int w = (blockIdx.x * blockDim.x + threadIdx.x) >> 5;
    int lane = threadIdx.x & 31;
    if (w >= S_ * B_) return;
    int s = w >> 5;        // B_ == 32
    int b = w & 31;
    const float* wh = g_Wh + (size_t)(s * B_ + b) * E_;
    const float* base = g_base + (size_t)b * E_;
    float cov = g_cov[b * S_ + s];
    float acc = 0.0f;
#pragma unroll
    for (int i = 0; i < 8; i++) {
        int f = (i * 32 + lane) * 4;
        float4 whv = *(const float4*)&wh[f];
        float4 bv  = *(const float4*)&base[f];
        float4 wcv = *(const float4*)&W_c[f];
        float4 vv  = *(const float4*)&V[f];
        acc += fast_tanh(whv.x + bv.x + cov * wcv.x) * vv.x;
        acc += fast_tanh(whv.y + bv.y + cov * wcv.y) * vv.y;
        acc += fast_tanh(whv.z + bv.z + cov * wcv.z) * vv.z;
        acc += fast_tanh(whv.w + bv.w + cov * wcv.w) * vv.w;
    }
#pragma unroll
    for (int o = 16; o > 0; o >>= 1) acc += __shfl_xor_sync(0xffffffffu, acc, o);
    if (lane == 0) {
        float m = x_mask[s * B_ + b];
        g_score[b * S_ + s] = (m == 0.0f) ? -1e9f : m * acc;
    }
}

// ---------------- softmax over S per b; also writes aw/cov outputs ----------------
__global__ __launch_bounds__(512) void k_softmax(
    float* __restrict__ out_aw, float* __restrict__ out_cov, int t) {
    int b = blockIdx.x;
    int tid = threadIdx.x;
    int lane = tid & 31, wid = tid >> 5;
    __shared__ float red[16];
    __shared__ float bcast;
    float v = (tid < S_) ? g_score[b * S_ + tid] : -3.0e38f;
    float m = v;
#pragma unroll
    for (int o = 16; o > 0; o >>= 1) m = fmaxf(m, __shfl_xor_sync(0xffffffffu, m, o));
    if (lane == 0) red[wid] = m;
    __syncthreads();
    if (tid == 0) {
        float x = red[0];
        for (int i = 1; i < 16; i++) x = fmaxf(x, red[i]);
        bcast = x;
    }
    __syncthreads();
    float mx = bcast;
    float e = (tid < S_) ? __expf(v - mx) : 0.0f;
    float sm = e;
#pragma unroll
    for (int o = 16; o > 0; o >>= 1) sm += __shfl_xor_sync(0xffffffffu, sm, o);
    __syncthreads();
    if (lane == 0) red[wid] = sm;
    __syncthreads();
    if (tid == 0) {
        float x = 0.0f;
        for (int i = 0; i < 16; i++) x += red[i];
        bcast = __fdividef(1.0f, x);
    }
    __syncthreads();
    float inv = bcast;
    if (tid < S_) {
        float aw = e * inv;
        g_aw[b * S_ + tid] = aw;
        out_aw[((size_t)t * B_ + b) * S_ + tid] = aw;
        float c = g_cov[b * S_ + tid];
        out_cov[((size_t)t * B_ + b) * S_ + tid] = c;   // coverage BEFORE update
        g_cov[b * S_ + tid] = c + aw;
    }
}

// ---------------- context: ctx[b][e] = sum_s aw[b][s] * enc[s][b][e] ----------------
__global__ __launch_bounds__(256) void k_ctx(
    const float* __restrict__ enc, float* __restrict__ out_ctx, int t) {
    int b = blockIdx.x >> 2;
    int e = (blockIdx.x & 3) * 256 + threadIdx.x;
    __shared__ float aw_s[S_];
    for (int i = threadIdx.x; i < S_; i += 256) aw_s[i] = g_aw[b * S_ + i];
    __syncthreads();
    const float* ep = enc + (size_t)b * E_ + e;
    float acc = 0.0f;
#pragma unroll 8
    for (int s = 0; s < S_; s++)
        acc += aw_s[s] * ep[(size_t)s * (B_ * E_)];
    g_ctx[b * E_ + e] = acc;
    out_ctx[((size_t)t * B_ + b) * E_ + e] = acc;
}

// ---------------- GRU2 finish: reduce split-K, gates, mask, write state + output ----------------
__global__ void k_gru2_finish(const float* __restrict__ b_ih2,
                              const float* __restrict__ b_hh2,
                              const float* __restrict__ y_mask,
                              float* __restrict__ out_h, int t) {
    int i = blockIdx.x * blockDim.x + threadIdx.x;  // B*H
    if (i >= B_ * H_) return;
    int b = i / H_, idx = i % H_;
    float s1 = g_s1[i];
    float gir = b_ih2[idx], giz = b_ih2[H_ + idx], gin = b_ih2[2 * H_ + idx];
    float ghr = b_hh2[idx], ghz = b_hh2[H_ + idx], ghn = b_hh2[2 * H_ + idx];
#pragma unroll
    for (int c = 0; c < KSPLIT; c++) {
        const float* pi = g_p_gi2 + ((size_t)c * B_ + b) * G3_;
        const float* ph = g_p_gh2 + ((size_t)c * B_ + b) * G3_;
        gir += pi[idx]; giz += pi[H_ + idx]; gin += pi[2 * H_ + idx];
        ghr += ph[idx]; ghz += ph[H_ + idx]; ghn += ph[2 * H_ + idx];
    }
    float r = fast_sigmoid(gir + ghr);
    float z = fast_sigmoid(giz + ghz);
    float n = fast_tanh(gin + r * ghn);
    float s = (1.0f - z) * n + z * s1;
    float ym = y_mask[t * B_ + b];
    float s2 = ym * s + (1.0f - ym) * s1;
    g_h[i] = s2;
    out_h[((size_t)t * B_ + b) * H_ + idx] = s2;
}

// ---------------- host launcher ----------------
extern "C" void kernel_launch(void* const* d_in, const int* in_sizes, int n_in,
                              void* d_out, int out_size) {
    const float* emb        = (const float*)d_in[0];
    const float* enc        = (const float*)d_in[1];
    const float* init_state = (const float*)d_in[2];
    const float* x_mask     = (const float*)d_in[3];
    const float* y_mask     = (const float*)d_in[4];
    const int*   x_index    = (const int*)  d_in[5];
    const float* init_cov   = (const float*)d_in[6];
    const float* W_h        = (const float*)d_in[7];
    const float* W_s        = (const float*)d_in[8];
    const float* W_c        = (const float*)d_in[9];
    const float* b_attn     = (const float*)d_in[10];
    const float* V          = (const float*)d_in[11];
    const float* w_ih1      = (const float*)d_in[12];
    const float* w_hh1      = (const float*)d_in[13];
    const float* b_ih1      = (const float*)d_in[14];
    const float* b_hh1      = (const float*)d_in[15];
    const float* w_ih2      = (const float*)d_in[16];
    const float* w_hh2      = (const float*)d_in[17];
    const float* b_ih2      = (const float*)d_in[18];
    const float* b_hh2      = (const float*)d_in[19];

    float* out     = (float*)d_out;
    float* out_h   = out;                               // (T,B,H)
    float* out_ctx = out_h + (size_t)T_ * B_ * H_;      // (T,B,E)
    float* out_aw  = out_ctx + (size_t)T_ * B_ * E_;    // (T,B,S)
    float* out_xi  = out_aw + (size_t)T_ * B_ * S_;     // (T,B,S)
    float* out_cov = out_xi + (size_t)T_ * B_ * S_;     // (T,B,S)

    float *p_Wh, *p_gi1, *p_h, *p_s1, *p_ctx, *p_pgh1, *p_pbase, *p_pgh2, *p_pgi2;
    cudaGetSymbolAddress((void**)&p_Wh, g_Wh);
    cudaGetSymbolAddress((void**)&p_gi1, g_gi1);
    cudaGetSymbolAddress((void**)&p_h, g_h);
    cudaGetSymbolAddress((void**)&p_s1, g_s1);
    cudaGetSymbolAddress((void**)&p_ctx, g_ctx);
    cudaGetSymbolAddress((void**)&p_pgh1, g_p_gh1);
    cudaGetSymbolAddress((void**)&p_pbase, g_p_base);
    cudaGetSymbolAddress((void**)&p_pgh2, g_p_gh2);
    cudaGetSymbolAddress((void**)&p_pgi2, g_p_gi2);

    // init state/coverage + x_indexes output
    k_init<<<256, 256>>>(init_state, init_cov, x_index, out_xi);

    // Wh_enc = enc @ W_h^T  : M=12800, N=1024, K=1024
    {
        dim3 g(E_ / 128, (S_ * B_) / 128);
        k_sgemm_nt<<<g, 256>>>(enc, W_h, nullptr, p_Wh, S_ * B_, E_, E_);
    }
    // gi1 = emb @ w_ih1^T + b_ih1 : M=2048, N=1536, K=128
    {
        dim3 g(G3_ / 128, (T_ * B_) / 128);
        k_sgemm_nt<<<g, 256>>>(emb, w_ih1, b_ih1, p_gi1, T_ * B_, G3_, I_);
    }

    for (int t = 0; t < T_; t++) {
        // gh1 = h @ w_hh1^T (split-K partials)
        k_gemm_smallB<<<dim3(G3_ / 128, KSPLIT), 256>>>(p_h, w_hh1, p_pgh1, G3_, H_);
        k_gru1_finish<<<(B_ * H_ + 255) / 256, 256>>>(b_hh1, y_mask, t);
        // base = s1 @ W_s^T ; gh2 = s1 @ w_hh2^T
        k_gemm_smallB<<<dim3(E_ / 128, KSPLIT), 256>>>(p_s1, W_s, p_pbase, E_, H_);
        k_gemm_smallB<<<dim3(G3_ / 128, KSPLIT), 256>>>(p_s1, w_hh2, p_pgh2, G3_, H_);
        k_base_finish<<<(B_ * E_ + 255) / 256, 256>>>(b_attn);
        // attention scores (warp per (s,b))
        k_score<<<(S_ * B_) / 8, 256>>>(x_mask, W_c, V);
        // softmax + aw/coverage outputs + coverage update
        k_softmax<<<B_, 512>>>(out_aw, out_cov, t);
        // context + ctx output
        k_ctx<<<B_ * 4, 256>>>(enc, out_ctx, t);
        // gi2 = ctx @ w_ih2^T
        k_gemm_smallB<<<dim3(G3_ / 128, KSPLIT), 256>>>(p_ctx, w_ih2, p_pgi2, G3_, E_);
        // GRU2 finish -> new h, hidden_states output
        k_gru2_finish<<<(B_ * H_ + 255) / 256, 256>>>(b_ih2, b_hh2, y_mask, out_h, t);
    }
}

// round 3
// speedup vs baseline: 1.2102x; 1.2102x over previous
#include <cuda_runtime.h>

#define T_ 64
#define S_ 400
#define B_ 32
#define H_ 512
#define E_ 1024
#define I_ 128
#define G3_ 1536
#define KSPLIT 16

// ---------------- persistent device scratch ----------------
__device__ float g_Wh[(size_t)S_ * B_ * E_];      // 52.4 MB : enc @ W_h^T
__device__ float g_gi1[(size_t)T_ * B_ * G3_];    // 12.6 MB : emb @ w_ih1^T + b_ih1
__device__ float g_h[B_ * H_];
__device__ float g_s1[B_ * H_];
__device__ float g_base[B_ * E_];                 // s1 @ W_s^T + b_attn
__device__ float g_score[B_ * S_];
__device__ float g_cov[B_ * S_];
__device__ float g_ctx[B_ * E_];
__device__ float g_p_gh1[KSPLIT * B_ * G3_];
__device__ float g_p_base[KSPLIT * B_ * E_];
__device__ float g_p_gh2[KSPLIT * B_ * G3_];
__device__ float g_p_gi2[KSPLIT * B_ * G3_];

// ---------------- math helpers ----------------
__device__ __forceinline__ float fast_tanh(float x) {
    float e = __expf(2.0f * x);
    return 1.0f - __fdividef(2.0f, e + 1.0f);
}
__device__ __forceinline__ float fast_sigmoid(float x) {
    return __fdividef(1.0f, 1.0f + __expf(-x));
}

// ---------------- init ----------------
__global__ void k_init(const float* __restrict__ init_state,
                       const float* __restrict__ init_cov,
                       const int* __restrict__ x_index,
                       float* __restrict__ out_xi) {
    int i = blockIdx.x * blockDim.x + threadIdx.x;
    if (i < B_ * H_) g_h[i] = init_state[i];
    if (i < B_ * S_) g_cov[i] = init_cov[i];
    for (int j = i; j < T_ * B_ * S_; j += gridDim.x * blockDim.x) {
        int s = j % S_;
        int b = (j / S_) % B_;
        out_xi[j] = (float)x_index[s * B_ + b];
    }
}

// ---------------- big SGEMM: C = A @ W^T (+bias), BK=16, double-buffered ----------------
__global__ __launch_bounds__(256) void k_sgemm_nt(
    const float* __restrict__ A, const float* __restrict__ W,
    const float* __restrict__ bias, float* __restrict__ C,
    int M, int N, int K) {
    __shared__ float As[2][16][128];
    __shared__ float Bs[2][16][128];
    const int m0 = blockIdx.y * 128;
    const int n0 = blockIdx.x * 128;
    const int tid = threadIdx.x;
    const int tm = (tid / 16) * 8;
    const int tn = (tid % 16) * 8;
    const int lr = tid >> 1;
    const int lc = (tid & 1) * 8;

    float acc[8][8];
#pragma unroll
    for (int i = 0; i < 8; i++)
#pragma unroll
        for (int j = 0; j < 8; j++) acc[i][j] = 0.0f;

    const float* Ap = A + (size_t)(m0 + lr) * K + lc;
    const float* Wp = W + (size_t)(n0 + lr) * K + lc;

    float4 pa0 = *(const float4*)(Ap + 0);
    float4 pa1 = *(const float4*)(Ap + 4);
    float4 pb0 = *(const float4*)(Wp + 0);
    float4 pb1 = *(const float4*)(Wp + 4);

    As[0][lc + 0][lr] = pa0.x; As[0][lc + 1][lr] = pa0.y; As[0][lc + 2][lr] = pa0.z; As[0][lc + 3][lr] = pa0.w;
    As[0][lc + 4][lr] = pa1.x; As[0][lc + 5][lr] = pa1.y; As[0][lc + 6][lr] = pa1.z; As[0][lc + 7][lr] = pa1.w;
    Bs[0][lc + 0][lr] = pb0.x; Bs[0][lc + 1][lr] = pb0.y; Bs[0][lc + 2][lr] = pb0.z; Bs[0][lc + 3][lr] = pb0.w;
    Bs[0][lc + 4][lr] = pb1.x; Bs[0][lc + 5][lr] = pb1.y; Bs[0][lc + 6][lr] = pb1.z; Bs[0][lc + 7][lr] = pb1.w;
    __syncthreads();

    const int nt = K / 16;
    int buf = 0;
    for (int t = 0; t < nt; t++) {
        if (t + 1 < nt) {
            int k0 = (t + 1) * 16;
            pa0 = *(const float4*)(Ap + k0);
            pa1 = *(const float4*)(Ap + k0 + 4);
            pb0 = *(const float4*)(Wp + k0);
            pb1 = *(const float4*)(Wp + k0 + 4);
        }
#pragma unroll
        for (int kk = 0; kk < 16; kk++) {
            float4 a0 = *(const float4*)&As[buf][kk][tm];
            float4 a1 = *(const float4*)&As[buf][kk][tm + 4];
            float4 b0 = *(const float4*)&Bs[buf][kk][tn];
            float4 b1 = *(const float4*)&Bs[buf][kk][tn + 4];
            float a[8] = {a0.x, a0.y, a0.z, a0.w, a1.x, a1.y, a1.z, a1.w};
            float b[8] = {b0.x, b0.y, b0.z, b0.w, b1.x, b1.y, b1.z, b1.w};
#pragma unroll
            for (int i = 0; i < 8; i++)
#pragma unroll
                for (int j = 0; j < 8; j++) acc[i][j] += a[i] * b[j];
        }
        if (t + 1 < nt) {
            int nb = buf ^ 1;
            As[nb][lc + 0][lr] = pa0.x; As[nb][lc + 1][lr] = pa0.y; As[nb][lc + 2][lr] = pa0.z; As[nb][lc + 3][lr] = pa0.w;
            As[nb][lc + 4][lr] = pa1.x; As[nb][lc + 5][lr] = pa1.y; As[nb][lc + 6][lr] = pa1.z; As[nb][lc + 7][lr] = pa1.w;
            Bs[nb][lc + 0][lr] = pb0.x; Bs[nb][lc + 1][lr] = pb0.y; Bs[nb][lc + 2][lr] = pb0.z; Bs[nb][lc + 3][lr] = pb0.w;
            Bs[nb][lc + 4][lr] = pb1.x; Bs[nb][lc + 5][lr] = pb1.y; Bs[nb][lc + 6][lr] = pb1.z; Bs[nb][lc + 7][lr] = pb1.w;
            __syncthreads();
            buf = nb;
        }
    }
    float bfrag[8];
#pragma unroll
    for (int j = 0; j < 8; j++) bfrag[j] = bias ? bias[n0 + tn + j] : 0.0f;
#pragma unroll
    for (int i = 0; i < 8; i++) {
        size_t row = (size_t)(m0 + tm + i) * N + n0 + tn;
#pragma unroll
        for (int j = 0; j < 8; j++) C[row + j] = acc[i][j] + bfrag[j];
    }
}

// ---------------- small batch-32 split-K GEMM ----------------
__device__ __forceinline__ void small_gemm_body(
    const float* __restrict__ X, const float* __restrict__ W,
    float* __restrict__ part, int N, int n0, int Kstride, int KC, int kc) {
    const int k0 = kc * KC;
    const int tid = threadIdx.x;
    const int j = tid & 127;
    const int bg = tid >> 7;

    __shared__ float ws[128][33];
    __shared__ float xs[32][36];

    float acc[16];
#pragma unroll
    for (int u = 0; u < 16; u++) acc[u] = 0.0f;

    for (int kt = 0; kt < KC; kt += 32) {
        {
            int r = tid >> 1;
            int cb = (tid & 1) * 16;
#pragma unroll
            for (int u = 0; u < 4; u++) {
                float4 v = *(const float4*)&W[(size_t)(n0 + r) * Kstride + k0 + kt + cb + u * 4];
                ws[r][cb + u * 4 + 0] = v.x; ws[r][cb + u * 4 + 1] = v.y;
                ws[r][cb + u * 4 + 2] = v.z; ws[r][cb + u * 4 + 3] = v.w;
            }
        }
        {
            int b = tid >> 3;
            int c = (tid & 7) * 4;
            float4 v = *(const float4*)&X[(size_t)b * Kstride + k0 + kt + c];
            xs[c + 0][b] = v.x; xs[c + 1][b] = v.y; xs[c + 2][b] = v.z; xs[c + 3][b] = v.w;
        }
        __syncthreads();
#pragma unroll
        for (int kk = 0; kk < 32; kk++) {
            float wv = ws[j][kk];
            const float4* xr = (const float4*)&xs[kk][bg * 16];
            float4 x0 = xr[0], x1 = xr[1], x2 = xr[2], x3 = xr[3];
            acc[0]  += wv * x0.x; acc[1]  += wv * x0.y; acc[2]  += wv * x0.z; acc[3]  += wv * x0.w;
            acc[4]  += wv * x1.x; acc[5]  += wv * x1.y; acc[6]  += wv * x1.z; acc[7]  += wv * x1.w;
            acc[8]  += wv * x2.x; acc[9]  += wv * x2.y; acc[10] += wv * x2.z; acc[11] += wv * x2.w;
            acc[12] += wv * x3.x; acc[13] += wv * x3.y; acc[14] += wv * x3.z; acc[15] += wv * x3.w;
        }
        __syncthreads();
    }
    float* p = part + ((size_t)kc * B_ + bg * 16) * N + n0 + j;
#pragma unroll
    for (int u = 0; u < 16; u++) p[(size_t)u * N] = acc[u];
}

__global__ __launch_bounds__(256) void k_gemm_small(
    const float* __restrict__ X, const float* __restrict__ W,
    float* __restrict__ part, int N, int Kstride, int KC) {
    small_gemm_body(X, W, part, N, blockIdx.x * 128, Kstride, KC, blockIdx.y);
}

__global__ __launch_bounds__(256) void k_gemm_dual(
    const float* __restrict__ X,
    const float* __restrict__ W1, float* __restrict__ p1, int N1,
    const float* __restrict__ W2, float* __restrict__ p2, int N2,
    int Kstride, int KC) {
    int nb = blockIdx.x * 128;
    if (nb < N1) small_gemm_body(X, W1, p1, N1, nb, Kstride, KC, blockIdx.y);
    else         small_gemm_body(X, W2, p2, N2, nb - N1, Kstride, KC, blockIdx.y);
}

// ---------------- GRU1 finish ----------------
__global__ void k_gru1_finish(const float* __restrict__ b_hh1,
                              const float* __restrict__ y_mask, int t) {
    int i = blockIdx.x * blockDim.x + threadIdx.x;
    if (i >= B_ * H_) return;
    int b = i / H_, idx = i % H_;
    float h = g_h[i];
    const float* gi = g_gi1 + ((size_t)t * B_ + b) * G3_;
    float gir = gi[idx], giz = gi[H_ + idx], gin = gi[2 * H_ + idx];
    float ghr = b_hh1[idx], ghz = b_hh1[H_ + idx], ghn = b_hh1[2 * H_ + idx];
#pragma unroll
    for (int c = 0; c < KSPLIT; c++) {
        const float* p = g_p_gh1 + ((size_t)c * B_ + b) * G3_;
        ghr += p[idx]; ghz += p[H_ + idx]; ghn += p[2 * H_ + idx];
    }
    float r = fast_sigmoid(gir + ghr);
    float z = fast_sigmoid(giz + ghz);
    float n = fast_tanh(gin + r * ghn);
    float s = (1.0f - z) * n + z * h;
    float ym = y_mask[t * B_ + b];
    g_s1[i] = ym * s + (1.0f - ym) * h;
}

// ---------------- base finish ----------------
__global__ void k_base_finish(const float* __restrict__ b_attn) {
    int i = blockIdx.x * blockDim.x + threadIdx.x;
    if (i >= B_ * E_) return;
    int b = i / E_, f = i % E_;
    float v = b_attn[f];
#pragma unroll
    for (int c = 0; c < KSPLIT; c++)
        v += g_p_base[((size_t)c * B_ + b) * E_ + f];
    g_base[i] = v;
}

// ---------------- attention score: warp per (s,b) ----------------
__global__ __launch_bounds__(256) void k_score(
    const float* __restrict__ x_mask, const float* __restrict__ W_c,
    const float* __restrict__ V) {
    int w = (blockIdx.x * blockDim.x + threadIdx.x) >> 5;
    int lane = threadIdx.x & 31;
    if (w >= S_ * B_) return;
    int s = w >> 5;
    int b = w & 31;
    const float* wh = g_Wh + (size_t)(s * B_ + b) * E_;
    const float* base = g_base + (size_t)b * E_;
    float cov = g_cov[b * S_ + s];
    float acc = 0.0f;
#pragma unroll
    for (int i = 0; i < 8; i++) {
        int f = (i * 32 + lane) * 4;
        float4 whv = *(const float4*)&wh[f];
        float4 bv  = *(const float4*)&base[f];
        float4 wcv = *(const float4*)&W_c[f];
        float4 vv  = *(const float4*)&V[f];
        acc += fast_tanh(whv.x + bv.x + cov * wcv.x) * vv.x;
        acc += fast_tanh(whv.y + bv.y + cov * wcv.y) * vv.y;
        acc += fast_tanh(whv.z + bv.z + cov * wcv.z) * vv.z;
        acc += fast_tanh(whv.w + bv.w + cov * wcv.w) * vv.w;
    }
#pragma unroll
    for (int o = 16; o > 0; o >>= 1) acc += __shfl_xor_sync(0xffffffffu, acc, o);
    if (lane == 0) {
        float m = x_mask[s * B_ + b];
        g_score[b * S_ + s] = (m == 0.0f) ? -1e9f : m * acc;
    }
}

// ---------------- fused softmax + ctx ----------------
__global__ __launch_bounds__(128) void k_attn_ctx(
    const float* __restrict__ enc,
    float* __restrict__ out_aw, float* __restrict__ out_cov,
    float* __restrict__ out_ctx, int t) {
    const int b = blockIdx.y;
    const int ec = blockIdx.x;
    const int tid = threadIdx.x;
    const int lane = tid & 31, wid = tid >> 5;

    __shared__ float aw_s[S_];
    __shared__ float red[4];
    __shared__ float bc;

    float v[4];
#pragma unroll
    for (int i = 0; i < 4; i++) {
        int idx = i * 128 + tid;
        v[i] = (idx < S_) ? g_score[b * S_ + idx] : -3.0e38f;
    }
    float m = fmaxf(fmaxf(v[0], v[1]), fmaxf(v[2], v[3]));
#pragma unroll
    for (int o = 16; o > 0; o >>= 1) m = fmaxf(m, __shfl_xor_sync(0xffffffffu, m, o));
    if (lane == 0) red[wid] = m;
    __syncthreads();
    if (tid == 0) bc = fmaxf(fmaxf(red[0], red[1]), fmaxf(red[2], red[3]));
    __syncthreads();
    const float mx = bc;

    float e[4], sm = 0.0f;
#pragma unroll
    for (int i = 0; i < 4; i++) {
        int idx = i * 128 + tid;
        e[i] = (idx < S_) ? __expf(v[i] - mx) : 0.0f;
        sm += e[i];
    }
#pragma unroll
    for (int o = 16; o > 0; o >>= 1) sm += __shfl_xor_sync(0xffffffffu, sm, o);
    __syncthreads();
    if (lane == 0) red[wid] = sm;
    __syncthreads();
    if (tid == 0) bc = __fdividef(1.0f, red[0] + red[1] + red[2] + red[3]);
    __syncthreads();
    const float inv = bc;
#pragma unroll
    for (int i = 0; i < 4; i++) {
        int idx = i * 128 + tid;
        if (idx < S_) aw_s[idx] = e[i] * inv;
    }
    __syncthreads();

    if (ec == 0) {
        for (int idx = tid; idx < S_; idx += 128) {
            float aw = aw_s[idx];
            out_aw[((size_t)t * B_ + b) * S_ + idx] = aw;
            float c = g_cov[b * S_ + idx];
            out_cov[((size_t)t * B_ + b) * S_ + idx] = c;   // coverage BEFORE update
            g_cov[b * S_ + idx] = c + aw;
        }
    }

    const int eidx = ec * 128 + tid;
    const float* ep = enc + (size_t)b * E_ + eidx;
    float acc = 0.0f;
#pragma unroll 16
    for (int s = 0; s < S_; s++)
        acc += aw_s[s] * ep[(size_t)s * (B_ * E_)];
    g_ctx[b * E_ + eidx] = acc;
    out_ctx[((size_t)t * B_ + b) * E_ + eidx] = acc;
}

// ---------------- GRU2 finish ----------------
__global__ void k_gru2_finish(const float* __restrict__ b_ih2,
                              const float* __restrict__ b_hh2,
                              const float* __restrict__ y_mask,
                              float* __restrict__ out_h, int t) {
    int i = blockIdx.x * blockDim.x + threadIdx.x;
    if (i >= B_ * H_) return;
    int b = i / H_, idx = i % H_;
    float s1 = g_s1[i];
    float gir = b_ih2[idx], giz = b_ih2[H_ + idx], gin = b_ih2[2 * H_ + idx];
    float ghr = b_hh2[idx], ghz = b_hh2[H_ + idx], ghn = b_hh2[2 * H_ + idx];
#pragma unroll
    for (int c = 0; c < KSPLIT; c++) {
        const float* pi = g_p_gi2 + ((size_t)c * B_ + b) * G3_;
        const float* ph = g_p_gh2 + ((size_t)c * B_ + b) * G3_;
        gir += pi[idx]; giz += pi[H_ + idx]; gin += pi[2 * H_ + idx];
        ghr += ph[idx]; ghz += ph[H_ + idx]; ghn += ph[2 * H_ + idx];
    }
    float r = fast_sigmoid(gir + ghr);
    float z = fast_sigmoid(giz + ghz);
    float n = fast_tanh(gin + r * ghn);
    float s = (1.0f - z) * n + z * s1;
    float ym = y_mask[t * B_ + b];
    float s2 = ym * s + (1.0f - ym) * s1;
    g_h[i] = s2;
    out_h[((size_t)t * B_ + b) * H_ + idx] = s2;
}

// ---------------- host launcher ----------------
extern "C" void kernel_launch(void* const* d_in, const int* in_sizes, int n_in,
                              void* d_out, int out_size) {
    const float* emb        = (const float*)d_in[0];
    const float* enc        = (const float*)d_in[1];
    const float* init_state = (const float*)d_in[2];
    const float* x_mask     = (const float*)d_in[3];
    const float* y_mask     = (const float*)d_in[4];
    const int*   x_index    = (const int*)  d_in[5];
    const float* init_cov   = (const float*)d_in[6];
    const float* W_h        = (const float*)d_in[7];
    const float* W_s        = (const float*)d_in[8];
    const float* W_c        = (const float*)d_in[9];
    const float* b_attn     = (const float*)d_in[10];
    const float* V          = (const float*)d_in[11];
    const float* w_ih1      = (const float*)d_in[12];
    const float* w_hh1      = (const float*)d_in[13];
    const float* b_ih1      = (const float*)d_in[14];
    const float* b_hh1      = (const float*)d_in[15];
    const float* w_ih2      = (const float*)d_in[16];
    const float* w_hh2      = (const float*)d_in[17];
    const float* b_ih2      = (const float*)d_in[18];
    const float* b_hh2      = (const float*)d_in[19];

    float* out     = (float*)d_out;
    float* out_h   = out;                               // (T,B,H)
    float* out_ctx = out_h + (size_t)T_ * B_ * H_;      // (T,B,E)
    float* out_aw  = out_ctx + (size_t)T_ * B_ * E_;    // (T,B,S)
    float* out_xi  = out_aw + (size_t)T_ * B_ * S_;     // (T,B,S)
    float* out_cov = out_xi + (size_t)T_ * B_ * S_;     // (T,B,S)

    float *p_Wh, *p_gi1, *p_h, *p_s1, *p_ctx, *p_pgh1, *p_pbase, *p_pgh2, *p_pgi2;
    cudaGetSymbolAddress((void**)&p_Wh, g_Wh);
    cudaGetSymbolAddress((void**)&p_gi1, g_gi1);
    cudaGetSymbolAddress((void**)&p_h, g_h);
    cudaGetSymbolAddress((void**)&p_s1, g_s1);
    cudaGetSymbolAddress((void**)&p_ctx, g_ctx);
    cudaGetSymbolAddress((void**)&p_pgh1, g_p_gh1);
    cudaGetSymbolAddress((void**)&p_pbase, g_p_base);
    cudaGetSymbolAddress((void**)&p_pgh2, g_p_gh2);
    cudaGetSymbolAddress((void**)&p_pgi2, g_p_gi2);

    k_init<<<256, 256>>>(init_state, init_cov, x_index, out_xi);

    // Wh_enc = enc @ W_h^T : M=12800, N=1024, K=1024
    k_sgemm_nt<<<dim3(E_ / 128, (S_ * B_) / 128), 256>>>(enc, W_h, nullptr, p_Wh, S_ * B_, E_, E_);
    // gi1 = emb @ w_ih1^T + b_ih1 : M=2048, N=1536, K=128
    k_sgemm_nt<<<dim3(G3_ / 128, (T_ * B_) / 128), 256>>>(emb, w_ih1, b_ih1, p_gi1, T_ * B_, G3_, I_);

    for (int t = 0; t < T_; t++) {
        k_gemm_small<<<dim3(G3_ / 128, KSPLIT), 256>>>(p_h, w_hh1, p_pgh1, G3_, H_, H_ / KSPLIT);
        k_gru1_finish<<<(B_ * H_) / 128, 128>>>(b_hh1, y_mask, t);
        k_gemm_dual<<<dim3((E_ + G3_) / 128, KSPLIT), 256>>>(
            p_s1, W_s, p_pbase, E_, w_hh2, p_pgh2, G3_, H_, H_ / KSPLIT);
        k_base_finish<<<(B_ * E_) / 128, 128>>>(b_attn);
        k_score<<<(S_ * B_) / 8, 256>>>(x_mask, W_c, V);
        k_attn_ctx<<<dim3(E_ / 128, B_), 128>>>(enc, out_aw, out_cov, out_ctx, t);
        k_gemm_small<<<dim3(G3_ / 128, KSPLIT), 256>>>(p_ctx, w_ih2, p_pgi2, G3_, E_, E_ / KSPLIT);
        k_gru2_finish<<<(B_ * H_) / 128, 128>>>(b_ih2, b_hh2, y_mask, out_h, t);
    }
}